// round 15
// baseline (speedup 1.0000x reference)
#include <cuda_runtime.h>
#include <cstdint>

#define Bq   128
#define Sq   512
#define Eq   256
#define HDq  256
#define Gq   1024
#define NTq  9

// ---- scratch (device globals; no allocation allowed) ----
__device__ float  g_xg[2][Sq][Bq][Gq];       // [dir][s][b][p] permuted gates (+bias)
__device__ float  g_h[Bq][Sq][2*HDq];        // [b][s][dir*256+j]
__device__ float  g_em[Bq][Sq][NTq];         // emissions
__device__ int    g_len[Bq];
__device__ unsigned g_cnt[2][8];             // per-(dir,batch-group) step counters
__device__ float  g_llh[Bq];

typedef unsigned long long ull;

__device__ __forceinline__ ull pk2(float x, float y){
    ull r; asm("mov.b64 %0, {%1, %2};" : "=l"(r) : "f"(x), "f"(y)); return r;
}
__device__ __forceinline__ float2 up2(ull v){
    float2 r; asm("mov.b64 {%0, %1}, %2;" : "=f"(r.x), "=f"(r.y) : "l"(v)); return r;
}
__device__ __forceinline__ ull fma2(ull a, ull b, ull c){
    ull d; asm("fma.rn.f32x2 %0, %1, %2, %3;" : "=l"(d) : "l"(a), "l"(b), "l"(c)); return d;
}
__device__ __forceinline__ float tanhfast(float x){
    float y; asm("tanh.approx.f32 %0, %1;" : "=f"(y) : "f"(x)); return y;
}
__device__ __forceinline__ float sigf(float x){ return 0.5f*tanhfast(0.5f*x) + 0.5f; }

__device__ __forceinline__ uint32_t smem_u32(const void* p){
    uint32_t a;
    asm("{ .reg .u64 t; cvta.to.shared.u64 t, %1; cvt.u32.u64 %0, t; }"
        : "=r"(a) : "l"(p));
    return a;
}
__device__ __forceinline__ void cpasync16(uint32_t dst, const void* src){
    asm volatile("cp.async.ca.shared.global [%0], [%1], 16;" :: "r"(dst), "l"(src));
}

// ---------------------------------------------------------------------------
// prep: reset barrier counters, detect mask dtype, compute per-row lengths
// ---------------------------------------------------------------------------
__global__ void k_prep(const void* __restrict__ mask){
    const int b = threadIdx.x;
    if (b < 16) g_cnt[b >> 3][b & 7] = 0u;
    const unsigned char* m8 = (const unsigned char*)mask;
    const bool u8 = (m8[1] != 0);
    const int* m32 = (const int*)mask;
    int cnt = 0;
    for (int s = 0; s < Sq; s++)
        cnt += u8 ? (m8[b*Sq + s] != 0) : (m32[b*Sq + s] != 0);
    g_len[b] = cnt;
}

// no-op: keep ncu's profiled slot (4th launch) on k_lstm
__global__ void k_nop(){}

// ---------------------------------------------------------------------------
// input projection: R6 config (best measured) — 8x8/thread, 2 CTAs/SM,
// float2 A-loads, f32x2 packed FMA; bias folded into output
// permutation: p = j*4 + q  (q in {i,f,g,o}), r0 = q*256 + j
// ---------------------------------------------------------------------------
__global__ void __launch_bounds__(256,2) k_inproj(
    const int*   __restrict__ X,   const float* __restrict__ emb,
    const float* __restrict__ wf,  const float* __restrict__ wb,
    const float* __restrict__ bif, const float* __restrict__ bhf,
    const float* __restrict__ bib, const float* __restrict__ bhb)
{
    extern __shared__ float sm[];
    float* As = sm;                 // [128][68]
    float* Bs = sm + 128*68;        // [64][132] (transposed weights)
    const int s   = blockIdx.x;
    const int nt  = blockIdx.y;
    const int dir = nt >> 3;
    const float* __restrict__ w = dir ? wb : wf;
    const int t  = threadIdx.x;
    const int ty = t >> 4, tx = t & 15;

    const int ar = t >> 1, ah = t & 1;
    const int token = X[ar*Sq + s];
    const float4* asrc = reinterpret_cast<const float4*>(emb + (size_t)token*Eq);

    const int bn = t & 127, bhv = t >> 7;
    const int p_b  = ((nt & 7) * 128) + bn;
    const int r0_b = (p_b & 3)*HDq + (p_b >> 2);
    const float4* bsrc = reinterpret_cast<const float4*>(w + (size_t)r0_b*Eq);

    ull acc2[8][4];
    #pragma unroll
    for (int i = 0; i < 8; i++)
        #pragma unroll
        for (int j = 0; j < 4; j++) acc2[i][j] = 0ull;

    for (int kt = 0; kt < 4; kt++){
        {
            float4* adst = reinterpret_cast<float4*>(As + ar*68 + ah*32);
            const float4* a4 = asrc + kt*16 + ah*8;
            #pragma unroll
            for (int i = 0; i < 8; i++) adst[i] = a4[i];
        }
        {
            const float4* b4 = bsrc + kt*16 + bhv*8;
            #pragma unroll
            for (int i = 0; i < 8; i++){
                float4 v = b4[i];
                int k0 = bhv*32 + i*4;
                Bs[(k0+0)*132 + bn] = v.x;
                Bs[(k0+1)*132 + bn] = v.y;
                Bs[(k0+2)*132 + bn] = v.z;
                Bs[(k0+3)*132 + bn] = v.w;
            }
        }
        __syncthreads();
        #pragma unroll 2
        for (int k = 0; k < 64; k += 2){
            ulonglong2 b00 = *reinterpret_cast<ulonglong2*>(Bs + k*132 + tx*8);
            ulonglong2 b01 = *reinterpret_cast<ulonglong2*>(Bs + k*132 + tx*8 + 4);
            ulonglong2 b10 = *reinterpret_cast<ulonglong2*>(Bs + (k+1)*132 + tx*8);
            ulonglong2 b11 = *reinterpret_cast<ulonglong2*>(Bs + (k+1)*132 + tx*8 + 4);
            #pragma unroll
            for (int i = 0; i < 8; i++){
                float2 av = *reinterpret_cast<const float2*>(As + (ty*8+i)*68 + k);
                ull a0 = pk2(av.x, av.x);
                ull a1 = pk2(av.y, av.y);
                acc2[i][0] = fma2(a0, b00.x, acc2[i][0]);
                acc2[i][1] = fma2(a0, b00.y, acc2[i][1]);
                acc2[i][2] = fma2(a0, b01.x, acc2[i][2]);
                acc2[i][3] = fma2(a0, b01.y, acc2[i][3]);
                acc2[i][0] = fma2(a1, b10.x, acc2[i][0]);
                acc2[i][1] = fma2(a1, b10.y, acc2[i][1]);
                acc2[i][2] = fma2(a1, b11.x, acc2[i][2]);
                acc2[i][3] = fma2(a1, b11.y, acc2[i][3]);
            }
        }
        __syncthreads();
    }

    const float* bi  = dir ? bib : bif;
    const float* bh2 = dir ? bhb : bhf;
    const int pbase = (nt & 7)*128 + tx*8;
    float bias[8];
    #pragma unroll
    for (int j = 0; j < 8; j++){
        int p  = pbase + j;
        int r0 = (p & 3)*HDq + (p >> 2);
        bias[j] = bi[r0] + bh2[r0];
    }
    #pragma unroll
    for (int i = 0; i < 8; i++){
        int bidx = ty*8 + i;
        float* dst = &g_xg[dir][s][bidx][pbase];
        float2 v0 = up2(acc2[i][0]);
        float2 v1 = up2(acc2[i][1]);
        float2 v2 = up2(acc2[i][2]);
        float2 v3 = up2(acc2[i][3]);
        float4 o0 = make_float4(v0.x+bias[0], v0.y+bias[1], v1.x+bias[2], v1.y+bias[3]);
        float4 o1 = make_float4(v2.x+bias[4], v2.y+bias[5], v3.x+bias[6], v3.y+bias[7]);
        reinterpret_cast<float4*>(dst)[0] = o0;
        reinterpret_cast<float4*>(dst)[1] = o1;
    }
}

// ---------------------------------------------------------------------------
// per-phase h-GEMM: 1 quad per thread, full k=256
// ---------------------------------------------------------------------------
__device__ __forceinline__ void gemm_q(
    const float* __restrict__ hrow, const float* __restrict__ Ws, int col,
    ull& Q0, ull& Q1)
{
    #pragma unroll 4
    for (int k = 0; k < HDq; k += 4){
        float4 a = *reinterpret_cast<const float4*>(hrow + k);
        ulonglong2 w0 = *reinterpret_cast<const ulonglong2*>(Ws + (k+0)*68 + col);
        { ull u = pk2(a.x, a.x); Q0 = fma2(u, w0.x, Q0); Q1 = fma2(u, w0.y, Q1); }
        ulonglong2 w1 = *reinterpret_cast<const ulonglong2*>(Ws + (k+1)*68 + col);
        { ull u = pk2(a.y, a.y); Q0 = fma2(u, w1.x, Q0); Q1 = fma2(u, w1.y, Q1); }
        ulonglong2 w2 = *reinterpret_cast<const ulonglong2*>(Ws + (k+2)*68 + col);
        { ull u = pk2(a.z, a.z); Q0 = fma2(u, w2.x, Q0); Q1 = fma2(u, w2.y, Q1); }
        ulonglong2 w3 = *reinterpret_cast<const ulonglong2*>(Ws + (k+3)*68 + col);
        { ull u = pk2(a.w, a.w); Q0 = fma2(u, w3.x, Q0); Q1 = fma2(u, w3.y, Q1); }
    }
}

// ---------------------------------------------------------------------------
// BiLSTM recurrence with batch-group PING-PONG:
// 128 CTAs = 2 dirs x 4 bg-pairs x 16 gate-slices(64 cols).
// Each CTA owns TWO batch-groups (bgA=pair*2, bgB=pair*2+1). While one
// group's h(t-1) propagates through L2 + gathers, the CTA computes the
// OTHER group's phase — the inter-CTA wait is shadowed by real work.
// thread: 1 row x 1 i/f/g/o quad per phase; warp = 4 rows x 32 cols.
// permutation: p = j*4 + q, source row r0 = q*256 + j
// ---------------------------------------------------------------------------
__global__ void __launch_bounds__(256,1) k_lstm(
    const float* __restrict__ whf, const float* __restrict__ whb)
{
    extern __shared__ float sm[];
    float* Ws  = sm;                 // [256][68]  w_hh slice (64 cols)
    float* HsA = sm + 256*68;        // [16][260]  gathered h for bgA
    float* HsB = HsA + 16*260;       // [16][260]  gathered h for bgB
    const int cta = blockIdx.x;
    const int dir  = cta >> 6;
    const int rem  = cta & 63;
    const int pair = rem >> 4;       // 0..3
    const int sl   = rem & 15;       // 64-col gate slice
    const int bgA  = pair*2, bgB = pair*2 + 1;
    const float* __restrict__ w = dir ? whb : whf;
    const int t = threadIdx.x;
    unsigned* cntA = &g_cnt[dir][bgA];
    unsigned* cntB = &g_cnt[dir][bgB];
    const uint32_t hsA_u32 = smem_u32(HsA);
    const uint32_t hsB_u32 = smem_u32(HsB);

    // ---- load + transpose weight slice (64 permuted cols, full k) ----
    {
        int c  = t & 63;
        int kq = t >> 6;
        int p  = sl*64 + c;
        int r0 = (p & 3)*HDq + (p >> 2);
        const float4* src = reinterpret_cast<const float4*>(w + (size_t)r0*HDq) + kq*16;
        #pragma unroll
        for (int i = 0; i < 16; i++){
            float4 v = src[i];
            int k0 = kq*64 + i*4;
            Ws[(k0+0)*68 + c] = v.x;
            Ws[(k0+1)*68 + c] = v.y;
            Ws[(k0+2)*68 + c] = v.z;
            Ws[(k0+3)*68 + c] = v.w;
        }
    }
    __syncthreads();

    // ---- thread tile: warp = (wr 0..3, wc 0..1); lane = (r4, c8) ----
    const int warp = t >> 5, lane = t & 31;
    const int wr = warp >> 1, wc = warp & 1;
    const int r4 = lane >> 3, c8 = lane & 7;
    const int row  = wr*4 + r4;          // 0..15
    const int quad = wc*8 + c8;          // 0..15
    const int col  = quad*4;             // 0..63
    const int j    = sl*16 + quad;       // h element index
    const int rowA = bgA*16 + row;
    const int rowB = bgB*16 + row;
    const float* hrowA = HsA + row*260;
    const float* hrowB = HsB + row*260;

    float cA = 0.f, cB = 0.f;

    // prefetch x for step 0, both groups
    int tt0 = dir ? (Sq-1) : 0;
    float4 xA = *reinterpret_cast<const float4*>(&g_xg[dir][tt0][rowA][sl*64 + col]);
    float4 xB = *reinterpret_cast<const float4*>(&g_xg[dir][tt0][rowB][sl*64 + col]);

    for (int step = 0; step < Sq; step++){
        const int tt  = dir ? (Sq-1-step) : step;
        const int ttp = dir ? (Sq-step)   : (step-1);   // previous time (step>0)

        // ================= phase A =================
        if (step) asm volatile("cp.async.wait_group 0;" ::: "memory"); // gather_A done
        __syncthreads();
        {
            ull Q0 = pk2(xA.x, xA.y), Q1 = pk2(xA.z, xA.w);
            if (step) gemm_q(hrowA, Ws, col, Q0, Q1);
            float2 g0 = up2(Q0), g1 = up2(Q1);
            cA = sigf(g0.y)*cA + sigf(g0.x)*tanhfast(g1.x);
            float h = sigf(g1.y)*tanhfast(cA);
            g_h[rowA][tt][dir*HDq + j] = h;
        }
        __syncthreads();                         // hA stores done
        if (t == 0){
            asm volatile("red.release.gpu.global.add.u32 [%0], %1;"
                         :: "l"(cntA), "r"(1u) : "memory");
            if (step){                           // peers' h_B(step-1) published?
                const unsigned target = 16u*(unsigned)step;
                unsigned v;
                do {
                    asm volatile("ld.acquire.gpu.global.u32 %0, [%1];"
                                 : "=r"(v) : "l"(cntB) : "memory");
                } while (v < target);
            }
        }
        __syncthreads();
        if (step){                               // gather h_B(step-1) -> HsB (async)
            #pragma unroll
            for (int i = 0; i < 4; i++){
                int idx = t + i*256, r = idx >> 6, q = idx & 63;
                cpasync16(hsB_u32 + (uint32_t)((r*260 + q*4)*4),
                          &g_h[bgB*16 + r][ttp][dir*HDq + q*4]);
            }
            asm volatile("cp.async.commit_group;" ::: "memory");
        }

        // ================= phase B =================
        if (step) asm volatile("cp.async.wait_group 0;" ::: "memory"); // gather_B done
        __syncthreads();
        {
            ull Q0 = pk2(xB.x, xB.y), Q1 = pk2(xB.z, xB.w);
            if (step) gemm_q(hrowB, Ws, col, Q0, Q1);
            float2 g0 = up2(Q0), g1 = up2(Q1);
            cB = sigf(g0.y)*cB + sigf(g0.x)*tanhfast(g1.x);
            float h = sigf(g1.y)*tanhfast(cB);
            g_h[rowB][tt][dir*HDq + j] = h;
        }
        __syncthreads();                         // hB stores done
        if (t == 0){
            asm volatile("red.release.gpu.global.add.u32 [%0], %1;"
                         :: "l"(cntB), "r"(1u) : "memory");
            if (step + 1 < Sq){                  // peers' h_A(step) published?
                const unsigned target = 16u*(unsigned)(step+1);
                unsigned v;
                do {
                    asm volatile("ld.acquire.gpu.global.u32 %0, [%1];"
                                 : "=r"(v) : "l"(cntA) : "memory");
                } while (v < target);
            }
        }
        __syncthreads();
        if (step + 1 < Sq){
            // gather h_A(step) -> HsA (async; retires at next phase A)
            #pragma unroll
            for (int i = 0; i < 4; i++){
                int idx = t + i*256, r = idx >> 6, q = idx & 63;
                cpasync16(hsA_u32 + (uint32_t)((r*260 + q*4)*4),
                          &g_h[bgA*16 + r][tt][dir*HDq + q*4]);
            }
            asm volatile("cp.async.commit_group;" ::: "memory");

            // prefetch x for step+1 (both groups) — hidden under next GEMMs
            const int tn = dir ? (Sq-2-step) : (step+1);
            xA = *reinterpret_cast<const float4*>(&g_xg[dir][tn][rowA][sl*64 + col]);
            xB = *reinterpret_cast<const float4*>(&g_xg[dir][tn][rowB][sl*64 + col]);
        }
    }
}

// ---------------------------------------------------------------------------
// emissions
// ---------------------------------------------------------------------------
__global__ void __launch_bounds__(256) k_emis(
    const float* __restrict__ lin_w, const float* __restrict__ lin_b)
{
    __shared__ float ws[NTq*512];
    const int t = threadIdx.x;
    for (int i = t; i < NTq*512; i += 256) ws[i] = lin_w[i];
    __syncthreads();
    const int warp = t >> 5, lane = t & 31;
    const int pos = blockIdx.x*8 + warp;
    const int b = pos >> 9, s = pos & 511;
    const float* orow = &g_h[b][s][0];
    float acc[NTq];
    #pragma unroll
    for (int k = 0; k < NTq; k++) acc[k] = 0.f;
    #pragma unroll 4
    for (int it = 0; it < 16; it++){
        float ov = orow[it*32 + lane];
        #pragma unroll
        for (int k = 0; k < NTq; k++) acc[k] += ov * ws[k*512 + it*32 + lane];
    }
    #pragma unroll
    for (int k = 0; k < NTq; k++){
        #pragma unroll
        for (int off = 16; off > 0; off >>= 1)
            acc[k] += __shfl_xor_sync(0xffffffffu, acc[k], off);
    }
    if (lane < NTq){
        float v = 0.f;
        #pragma unroll
        for (int k = 0; k < NTq; k++) if (lane == k) v = acc[k];
        g_em[b][s][lane] = v + lin_b[lane];
    }
}

// ---------------------------------------------------------------------------
// CRF log-likelihood: one warp per batch row
// ---------------------------------------------------------------------------
__global__ void __launch_bounds__(1024) k_crf(
    const int*   __restrict__ y,
    const float* __restrict__ st, const float* __restrict__ en,
    const float* __restrict__ tr)
{
    const int t = threadIdx.x;
    const int warp = t >> 5, lane = t & 31;
    const int b = blockIdx.x*32 + warp;
    const int L = g_len[b];
    const int* yr = y + b*Sq;
    const float* emr = &g_em[b][0][0];
    const int lc = (lane < NTq) ? lane : (NTq-1);

    float num = 0.f;
    for (int tt = lane; tt < L; tt += 32){
        int yt = yr[tt];
        num += emr[tt*NTq + yt];
        if (tt > 0) num += tr[yr[tt-1]*NTq + yt];
    }
    #pragma unroll
    for (int off = 16; off > 0; off >>= 1)
        num += __shfl_xor_sync(0xffffffffu, num, off);

    float trv[NTq];
    #pragma unroll
    for (int i = 0; i < NTq; i++) trv[i] = tr[i*NTq + lc];
    float alpha = st[lc] + emr[lc];
    for (int tt = 1; tt < L; tt++){
        float vals[NTq]; float m = -3.0e38f;
        #pragma unroll
        for (int i = 0; i < NTq; i++){
            float ai = __shfl_sync(0xffffffffu, alpha, i);
            vals[i] = ai + trv[i];
            m = fmaxf(m, vals[i]);
        }
        float ssum = 0.f;
        #pragma unroll
        for (int i = 0; i < NTq; i++) ssum += __expf(vals[i]-m);
        alpha = m + __logf(ssum) + emr[tt*NTq + lc];
    }
    float v = (lane < NTq) ? (alpha + en[lane]) : -3.0e38f;
    float m = v;
    #pragma unroll
    for (int off = 16; off > 0; off >>= 1)
        m = fmaxf(m, __shfl_xor_sync(0xffffffffu, m, off));
    float e = __expf(v - m);
    #pragma unroll
    for (int off = 16; off > 0; off >>= 1)
        e += __shfl_xor_sync(0xffffffffu, e, off);
    float den = m + __logf(e);
    if (lane == 0)
        g_llh[b] = num + st[yr[0]] + en[yr[L-1]] - den;
}

__global__ void k_finsum(float* __restrict__ out){
    const int lane = threadIdx.x;
    float s1 = g_llh[lane] + g_llh[lane+32] + g_llh[lane+64] + g_llh[lane+96];
    #pragma unroll
    for (int off = 16; off > 0; off >>= 1)
        s1 += __shfl_xor_sync(0xffffffffu, s1, off);
    if (lane == 0) out[0] = s1;
}

// ---------------------------------------------------------------------------
extern "C" void kernel_launch(void* const* d_in, const int* in_sizes, int n_in,
                              void* d_out, int out_size)
{
    const int*   X      = (const int*)  d_in[0];
    const int*   y      = (const int*)  d_in[1];
    const void*  mask   =               d_in[2];
    const float* emb    = (const float*)d_in[3];
    const float* w_ih_f = (const float*)d_in[4];
    const float* w_hh_f = (const float*)d_in[5];
    const float* b_ih_f = (const float*)d_in[6];
    const float* b_hh_f = (const float*)d_in[7];
    const float* w_ih_b = (const float*)d_in[8];
    const float* w_hh_b = (const float*)d_in[9];
    const float* b_ih_b = (const float*)d_in[10];
    const float* b_hh_b = (const float*)d_in[11];
    const float* lin_w  = (const float*)d_in[12];
    const float* lin_b  = (const float*)d_in[13];
    const float* st     = (const float*)d_in[14];
    const float* en     = (const float*)d_in[15];
    const float* tr     = (const float*)d_in[16];

    const int SMEM1 = (128*68 + 64*132) * 4;      // 68,608 B
    const int SMEM2 = (256*68 + 2*16*260) * 4;    // 102,912 B (Ws + HsA + HsB)
    cudaFuncSetAttribute(k_inproj, cudaFuncAttributeMaxDynamicSharedMemorySize, SMEM1);
    cudaFuncSetAttribute(k_lstm,   cudaFuncAttributeMaxDynamicSharedMemorySize, SMEM2);

    k_prep<<<1, 128>>>(mask);
    k_nop<<<1, 32>>>();   // ncu profiles the 4th launch -> k_lstm
    k_inproj<<<dim3(512, 16), 256, SMEM1>>>(X, emb, w_ih_f, w_ih_b,
                                            b_ih_f, b_hh_f, b_ih_b, b_hh_b);
    k_lstm<<<128, 256, SMEM2>>>(w_hh_f, w_hh_b);
    k_emis<<<8192, 256>>>(lin_w, lin_b);
    k_crf<<<4, 1024>>>(y, st, en, tr);
    k_finsum<<<1, 32>>>((float*)d_out);
}

// round 16
// speedup vs baseline: 1.4155x; 1.4155x over previous
#include <cuda_runtime.h>
#include <cstdint>

#define Bq   128
#define Sq   512
#define Eq   256
#define HDq  256
#define Gq   1024
#define NTq  9

// ---- scratch (device globals; no allocation allowed) ----
__device__ float g_xg[2][Sq][Bq][Gq];        // [dir][s][b][p] permuted gates
__device__ float g_h[Bq][Sq][2*HDq];         // [b][s][dir*256+j]
__device__ float g_em[Bq][Sq][NTq];          // emissions
__device__ int   g_len[Bq];
__device__ unsigned g_cnt[2][8];             // per-(dir,batch-group) step counters
__device__ float g_llh[Bq];

typedef unsigned long long ull;

__device__ __forceinline__ ull pk2(float x, float y){
    ull r; asm("mov.b64 %0, {%1, %2};" : "=l"(r) : "f"(x), "f"(y)); return r;
}
__device__ __forceinline__ float2 up2(ull v){
    float2 r; asm("mov.b64 {%0, %1}, %2;" : "=f"(r.x), "=f"(r.y) : "l"(v)); return r;
}
__device__ __forceinline__ ull fma2(ull a, ull b, ull c){
    ull d; asm("fma.rn.f32x2 %0, %1, %2, %3;" : "=l"(d) : "l"(a), "l"(b), "l"(c)); return d;
}
__device__ __forceinline__ float tanhfast(float x){
    float y; asm("tanh.approx.f32 %0, %1;" : "=f"(y) : "f"(x)); return y;
}
__device__ __forceinline__ float sigf(float x){ return 0.5f*tanhfast(0.5f*x) + 0.5f; }

__device__ __forceinline__ uint32_t smem_u32(const void* p){
    uint32_t a;
    asm("{ .reg .u64 t; cvta.to.shared.u64 t, %1; cvt.u32.u64 %0, t; }"
        : "=r"(a) : "l"(p));
    return a;
}
__device__ __forceinline__ void cpasync16(uint32_t dst, const void* src){
    asm volatile("cp.async.ca.shared.global [%0], [%1], 16;" :: "r"(dst), "l"(src));
}

// ---------------------------------------------------------------------------
// prep: reset barrier counters, detect mask dtype, compute per-row lengths
// ---------------------------------------------------------------------------
__global__ void k_prep(const void* __restrict__ mask){
    const int b = threadIdx.x;
    if (b < 16) g_cnt[b >> 3][b & 7] = 0u;
    const unsigned char* m8 = (const unsigned char*)mask;
    const bool u8 = (m8[1] != 0);
    const int* m32 = (const int*)mask;
    int cnt = 0;
    for (int s = 0; s < Sq; s++)
        cnt += u8 ? (m8[b*Sq + s] != 0) : (m32[b*Sq + s] != 0);
    g_len[b] = cnt;
}

// no-op: put ncu's profiled slot (4th launch) on k_lstm
__global__ void k_nop(){}

// ---------------------------------------------------------------------------
// input projection: R6 config (best measured) — 8x8/thread, 2 CTAs/SM,
// float2 A-loads, f32x2 packed FMA
// permutation: p = j*4 + q  (q in {i,f,g,o}), r0 = q*256 + j
// ---------------------------------------------------------------------------
__global__ void __launch_bounds__(256,2) k_inproj(
    const int*   __restrict__ X,   const float* __restrict__ emb,
    const float* __restrict__ wf,  const float* __restrict__ wb,
    const float* __restrict__ bif, const float* __restrict__ bhf,
    const float* __restrict__ bib, const float* __restrict__ bhb)
{
    extern __shared__ float sm[];
    float* As = sm;                 // [128][68]
    float* Bs = sm + 128*68;        // [64][132] (transposed weights)
    const int s   = blockIdx.x;
    const int nt  = blockIdx.y;
    const int dir = nt >> 3;
    const float* __restrict__ w = dir ? wb : wf;
    const int t  = threadIdx.x;
    const int ty = t >> 4, tx = t & 15;

    const int ar = t >> 1, ah = t & 1;
    const int token = X[ar*Sq + s];
    const float4* asrc = reinterpret_cast<const float4*>(emb + (size_t)token*Eq);

    const int bn = t & 127, bhv = t >> 7;
    const int p_b  = ((nt & 7) * 128) + bn;
    const int r0_b = (p_b & 3)*HDq + (p_b >> 2);
    const float4* bsrc = reinterpret_cast<const float4*>(w + (size_t)r0_b*Eq);

    ull acc2[8][4];
    #pragma unroll
    for (int i = 0; i < 8; i++)
        #pragma unroll
        for (int j = 0; j < 4; j++) acc2[i][j] = 0ull;

    for (int kt = 0; kt < 4; kt++){
        {
            float4* adst = reinterpret_cast<float4*>(As + ar*68 + ah*32);
            const float4* a4 = asrc + kt*16 + ah*8;
            #pragma unroll
            for (int i = 0; i < 8; i++) adst[i] = a4[i];
        }
        {
            const float4* b4 = bsrc + kt*16 + bhv*8;
            #pragma unroll
            for (int i = 0; i < 8; i++){
                float4 v = b4[i];
                int k0 = bhv*32 + i*4;
                Bs[(k0+0)*132 + bn] = v.x;
                Bs[(k0+1)*132 + bn] = v.y;
                Bs[(k0+2)*132 + bn] = v.z;
                Bs[(k0+3)*132 + bn] = v.w;
            }
        }
        __syncthreads();
        #pragma unroll 2
        for (int k = 0; k < 64; k += 2){
            ulonglong2 b00 = *reinterpret_cast<ulonglong2*>(Bs + k*132 + tx*8);
            ulonglong2 b01 = *reinterpret_cast<ulonglong2*>(Bs + k*132 + tx*8 + 4);
            ulonglong2 b10 = *reinterpret_cast<ulonglong2*>(Bs + (k+1)*132 + tx*8);
            ulonglong2 b11 = *reinterpret_cast<ulonglong2*>(Bs + (k+1)*132 + tx*8 + 4);
            #pragma unroll
            for (int i = 0; i < 8; i++){
                float2 av = *reinterpret_cast<const float2*>(As + (ty*8+i)*68 + k);
                ull a0 = pk2(av.x, av.x);
                ull a1 = pk2(av.y, av.y);
                acc2[i][0] = fma2(a0, b00.x, acc2[i][0]);
                acc2[i][1] = fma2(a0, b00.y, acc2[i][1]);
                acc2[i][2] = fma2(a0, b01.x, acc2[i][2]);
                acc2[i][3] = fma2(a0, b01.y, acc2[i][3]);
                acc2[i][0] = fma2(a1, b10.x, acc2[i][0]);
                acc2[i][1] = fma2(a1, b10.y, acc2[i][1]);
                acc2[i][2] = fma2(a1, b11.x, acc2[i][2]);
                acc2[i][3] = fma2(a1, b11.y, acc2[i][3]);
            }
        }
        __syncthreads();
    }

    const float* bi  = dir ? bib : bif;
    const float* bh2 = dir ? bhb : bhf;
    const int pbase = (nt & 7)*128 + tx*8;
    float bias[8];
    #pragma unroll
    for (int j = 0; j < 8; j++){
        int p  = pbase + j;
        int r0 = (p & 3)*HDq + (p >> 2);
        bias[j] = bi[r0] + bh2[r0];
    }
    #pragma unroll
    for (int i = 0; i < 8; i++){
        int bidx = ty*8 + i;
        float* dst = &g_xg[dir][s][bidx][pbase];
        float2 v0 = up2(acc2[i][0]);
        float2 v1 = up2(acc2[i][1]);
        float2 v2 = up2(acc2[i][2]);
        float2 v3 = up2(acc2[i][3]);
        float4 o0 = make_float4(v0.x+bias[0], v0.y+bias[1], v1.x+bias[2], v1.y+bias[3]);
        float4 o1 = make_float4(v2.x+bias[4], v2.y+bias[5], v3.x+bias[6], v3.y+bias[7]);
        reinterpret_cast<float4*>(dst)[0] = o0;
        reinterpret_cast<float4*>(dst)[1] = o1;
    }
}

// ---------------------------------------------------------------------------
// persistent BiLSTM recurrence: 128 CTAs x 256 threads (R6 topology, 5846us)
// sync: bar.sync -> red.release.gpu -> ld.acquire.gpu poll -> bar.sync
// h gather: 2 chunked cp.async groups overlapped with GEMM halves
// ---------------------------------------------------------------------------
__global__ void __launch_bounds__(256,1) k_lstm(
    const float* __restrict__ whf, const float* __restrict__ whb)
{
    extern __shared__ float sm[];
    float* Ws = sm;                 // [256][132]  Ws[k][col]
    float* Hs = sm + 256*132;       // [16][260]   Hs[row][k]
    const int cta = blockIdx.x;
    const int dir = cta >> 6;
    const int rem = cta & 63;
    const int bg  = rem >> 3;       // batch group (16 rows)
    const int sl  = rem & 7;        // 128 permuted-gate slice
    const float* __restrict__ w = dir ? whb : whf;
    const int t = threadIdx.x;
    unsigned* cntp = &g_cnt[dir][bg];
    const uint32_t hs_u32 = smem_u32(Hs);

    // load weight slice once (permuted columns), stored transposed [k][col]
    {
        int pl = t & 127;
        int kh = t >> 7;
        int p  = sl*128 + pl;
        int r0 = (p & 3)*HDq + (p >> 2);
        const float4* src = reinterpret_cast<const float4*>(w + (size_t)r0*HDq + kh*128);
        #pragma unroll
        for (int i = 0; i < 32; i++){
            float4 v = src[i];
            int k0 = kh*128 + i*4;
            Ws[(k0+0)*132 + pl] = v.x;
            Ws[(k0+1)*132 + pl] = v.y;
            Ws[(k0+2)*132 + pl] = v.z;
            Ws[(k0+3)*132 + pl] = v.w;
        }
    }
    __syncthreads();

    const int warp = t >> 5, lane = t & 31;
    const int cb = warp & 3, rh = warp >> 2;
    const int c4 = lane & 7, rp = lane >> 3;
    const int bcol   = cb*32 + c4*4;      // 4 consecutive permuted gates = 1 quad
    const int jloc   = cb*8 + c4;         // h element within slice (0..31)
    const int r0     = rh*8 + rp*2;       // rows r0, r0+1
    const int bgl0   = bg*16 + r0;
    const int bgl1   = bgl0 + 1;
    const float* hrA = Hs + r0*260;
    const float* hrB = Hs + (r0+1)*260;

    float cA = 0.f, cB = 0.f;

    // prefetch x for step 0
    int tt0 = dir ? (Sq-1) : 0;
    float4 xA = *reinterpret_cast<const float4*>(&g_xg[dir][tt0][bgl0][sl*128 + bcol]);
    float4 xB = *reinterpret_cast<const float4*>(&g_xg[dir][tt0][bgl1][sl*128 + bcol]);

    for (int step = 0; step < Sq; step++){
        const int tt = dir ? (Sq-1-step) : step;

        ull aA0 = pk2(xA.x, xA.y), aA1 = pk2(xA.z, xA.w);
        ull aB0 = pk2(xB.x, xB.y), aB1 = pk2(xB.z, xB.w);

        if (step){
            // two GEMM halves, each gated on its cp.async chunk
            #pragma unroll
            for (int half = 0; half < 2; half++){
                if (half == 0){
                    asm volatile("cp.async.wait_group 1;" ::: "memory");
                } else {
                    asm volatile("cp.async.wait_group 0;" ::: "memory");
                }
                __syncthreads();
                const int kbeg = half*128;
                #pragma unroll 2
                for (int k = kbeg; k < kbeg+128; k += 4){
                    float4 hA4 = *reinterpret_cast<const float4*>(hrA + k);
                    float4 hB4 = *reinterpret_cast<const float4*>(hrB + k);
                    ulonglong2 w0 = *reinterpret_cast<ulonglong2*>(Ws + (k+0)*132 + bcol);
                    {   ull a = pk2(hA4.x, hA4.x), b = pk2(hB4.x, hB4.x);
                        aA0 = fma2(a, w0.x, aA0);  aA1 = fma2(a, w0.y, aA1);
                        aB0 = fma2(b, w0.x, aB0);  aB1 = fma2(b, w0.y, aB1); }
                    ulonglong2 w1 = *reinterpret_cast<ulonglong2*>(Ws + (k+1)*132 + bcol);
                    {   ull a = pk2(hA4.y, hA4.y), b = pk2(hB4.y, hB4.y);
                        aA0 = fma2(a, w1.x, aA0);  aA1 = fma2(a, w1.y, aA1);
                        aB0 = fma2(b, w1.x, aB0);  aB1 = fma2(b, w1.y, aB1); }
                    ulonglong2 w2 = *reinterpret_cast<ulonglong2*>(Ws + (k+2)*132 + bcol);
                    {   ull a = pk2(hA4.z, hA4.z), b = pk2(hB4.z, hB4.z);
                        aA0 = fma2(a, w2.x, aA0);  aA1 = fma2(a, w2.y, aA1);
                        aB0 = fma2(b, w2.x, aB0);  aB1 = fma2(b, w2.y, aB1); }
                    ulonglong2 w3 = *reinterpret_cast<ulonglong2*>(Ws + (k+3)*132 + bcol);
                    {   ull a = pk2(hA4.w, hA4.w), b = pk2(hB4.w, hB4.w);
                        aA0 = fma2(a, w3.x, aA0);  aA1 = fma2(a, w3.y, aA1);
                        aB0 = fma2(b, w3.x, aB0);  aB1 = fma2(b, w3.y, aB1); }
                }
            }
        }
        // gates (i,f,g,o) per row
        float2 gA0 = up2(aA0), gA1 = up2(aA1);
        float2 gB0 = up2(aB0), gB1 = up2(aB1);
        cA = sigf(gA0.y)*cA + sigf(gA0.x)*tanhfast(gA1.x);
        float hAo = sigf(gA1.y)*tanhfast(cA);
        cB = sigf(gB0.y)*cB + sigf(gB0.x)*tanhfast(gB1.x);
        float hBo = sigf(gB1.y)*tanhfast(cB);

        g_h[bgl0][tt][dir*HDq + sl*32 + jloc] = hAo;
        g_h[bgl1][tt][dir*HDq + sl*32 + jloc] = hBo;

        if (step + 1 < Sq){
            const int tn = dir ? (Sq-2-step) : (step+1);
            // prefetch next step's x (hidden behind the barrier)
            xA = *reinterpret_cast<const float4*>(&g_xg[dir][tn][bgl0][sl*128 + bcol]);
            xB = *reinterpret_cast<const float4*>(&g_xg[dir][tn][bgl1][sl*128 + bcol]);

            // group-local barrier: release-arrive, acquire-poll (8 CTAs)
            __syncthreads();
            if (t == 0){
                asm volatile("red.release.gpu.global.add.u32 [%0], %1;"
                             :: "l"(cntp), "r"(1u) : "memory");
                const unsigned target = 8u*(unsigned)(step+1);
                unsigned v;
                do {
                    asm volatile("ld.acquire.gpu.global.u32 %0, [%1];"
                                 : "=r"(v) : "l"(cntp) : "memory");
                } while (v < target);
            }
            __syncthreads();

            // issue chunked h gather (2 groups of 128 k each); waited at next
            // step's GEMM halves
            #pragma unroll
            for (int c = 0; c < 2; c++){
                #pragma unroll
                for (int i = 0; i < 2; i++){
                    int idx = t + i*256;          // 0..511
                    int r   = idx >> 5;           // 0..15
                    int jjl = idx & 31;
                    int jj  = c*32 + jjl;         // float4 index: k = jj*4
                    cpasync16(hs_u32 + (uint32_t)((r*260 + jj*4)*4),
                              &g_h[bg*16 + r][tt][dir*HDq + jj*4]);
                }
                asm volatile("cp.async.commit_group;" ::: "memory");
            }
        }
    }
}

// ---------------------------------------------------------------------------
// emissions — float4 loads (4x MLP, 4x fewer LDG instructions; DRAM-bound)
// ---------------------------------------------------------------------------
__global__ void __launch_bounds__(256) k_emis(
    const float* __restrict__ lin_w, const float* __restrict__ lin_b)
{
    __shared__ float ws[NTq*512];
    const int t = threadIdx.x;
    for (int i = t; i < NTq*512; i += 256) ws[i] = lin_w[i];
    __syncthreads();
    const int warp = t >> 5, lane = t & 31;
    const int pos = blockIdx.x*8 + warp;
    const int b = pos >> 9, s = pos & 511;
    const float* orow = &g_h[b][s][0];
    float acc[NTq];
    #pragma unroll
    for (int k = 0; k < NTq; k++) acc[k] = 0.f;
    #pragma unroll
    for (int it = 0; it < 4; it++){
        float4 ov = *reinterpret_cast<const float4*>(orow + it*128 + lane*4);
        #pragma unroll
        for (int k = 0; k < NTq; k++){
            float4 wv = *reinterpret_cast<const float4*>(ws + k*512 + it*128 + lane*4);
            acc[k] += ov.x*wv.x + ov.y*wv.y + ov.z*wv.z + ov.w*wv.w;
        }
    }
    #pragma unroll
    for (int k = 0; k < NTq; k++){
        #pragma unroll
        for (int off = 16; off > 0; off >>= 1)
            acc[k] += __shfl_xor_sync(0xffffffffu, acc[k], off);
    }
    if (lane < NTq){
        float v = 0.f;
        #pragma unroll
        for (int k = 0; k < NTq; k++) if (lane == k) v = acc[k];
        g_em[b][s][lane] = v + lin_b[lane];
    }
}

// ---------------------------------------------------------------------------
// CRF log-likelihood: one warp per batch row
// ---------------------------------------------------------------------------
__global__ void __launch_bounds__(1024) k_crf(
    const int*   __restrict__ y,
    const float* __restrict__ st, const float* __restrict__ en,
    const float* __restrict__ tr)
{
    const int t = threadIdx.x;
    const int warp = t >> 5, lane = t & 31;
    const int b = blockIdx.x*32 + warp;
    const int L = g_len[b];
    const int* yr = y + b*Sq;
    const float* emr = &g_em[b][0][0];
    const int lc = (lane < NTq) ? lane : (NTq-1);

    float num = 0.f;
    for (int tt = lane; tt < L; tt += 32){
        int yt = yr[tt];
        num += emr[tt*NTq + yt];
        if (tt > 0) num += tr[yr[tt-1]*NTq + yt];
    }
    #pragma unroll
    for (int off = 16; off > 0; off >>= 1)
        num += __shfl_xor_sync(0xffffffffu, num, off);

    float trv[NTq];
    #pragma unroll
    for (int i = 0; i < NTq; i++) trv[i] = tr[i*NTq + lc];
    float alpha = st[lc] + emr[lc];
    for (int tt = 1; tt < L; tt++){
        float vals[NTq]; float m = -3.0e38f;
        #pragma unroll
        for (int i = 0; i < NTq; i++){
            float ai = __shfl_sync(0xffffffffu, alpha, i);
            vals[i] = ai + trv[i];
            m = fmaxf(m, vals[i]);
        }
        float ssum = 0.f;
        #pragma unroll
        for (int i = 0; i < NTq; i++) ssum += __expf(vals[i]-m);
        alpha = m + __logf(ssum) + emr[tt*NTq + lc];
    }
    float v = (lane < NTq) ? (alpha + en[lane]) : -3.0e38f;
    float m = v;
    #pragma unroll
    for (int off = 16; off > 0; off >>= 1)
        m = fmaxf(m, __shfl_xor_sync(0xffffffffu, m, off));
    float e = __expf(v - m);
    #pragma unroll
    for (int off = 16; off > 0; off >>= 1)
        e += __shfl_xor_sync(0xffffffffu, e, off);
    float den = m + __logf(e);
    if (lane == 0)
        g_llh[b] = num + st[yr[0]] + en[yr[L-1]] - den;
}

__global__ void k_finsum(float* __restrict__ out){
    const int lane = threadIdx.x;
    float s1 = g_llh[lane] + g_llh[lane+32] + g_llh[lane+64] + g_llh[lane+96];
    #pragma unroll
    for (int off = 16; off > 0; off >>= 1)
        s1 += __shfl_xor_sync(0xffffffffu, s1, off);
    if (lane == 0) out[0] = s1;
}

// ---------------------------------------------------------------------------
extern "C" void kernel_launch(void* const* d_in, const int* in_sizes, int n_in,
                              void* d_out, int out_size)
{
    const int*   X      = (const int*)  d_in[0];
    const int*   y      = (const int*)  d_in[1];
    const void*  mask   =               d_in[2];
    const float* emb    = (const float*)d_in[3];
    const float* w_ih_f = (const float*)d_in[4];
    const float* w_hh_f = (const float*)d_in[5];
    const float* b_ih_f = (const float*)d_in[6];
    const float* b_hh_f = (const float*)d_in[7];
    const float* w_ih_b = (const float*)d_in[8];
    const float* w_hh_b = (const float*)d_in[9];
    const float* b_ih_b = (const float*)d_in[10];
    const float* b_hh_b = (const float*)d_in[11];
    const float* lin_w  = (const float*)d_in[12];
    const float* lin_b  = (const float*)d_in[13];
    const float* st     = (const float*)d_in[14];
    const float* en     = (const float*)d_in[15];
    const float* tr     = (const float*)d_in[16];

    const int SMEM1 = (128*68 + 64*132) * 4;    // 68,608 B
    const int SMEM2 = (256*132 + 16*260) * 4;   // 151,808 B
    cudaFuncSetAttribute(k_inproj, cudaFuncAttributeMaxDynamicSharedMemorySize, SMEM1);
    cudaFuncSetAttribute(k_lstm,   cudaFuncAttributeMaxDynamicSharedMemorySize, SMEM2);

    k_prep<<<1, 128>>>(mask);
    k_nop<<<1, 32>>>();   // ncu profiles the 4th launch -> k_lstm
    k_inproj<<<dim3(512, 16), 256, SMEM1>>>(X, emb, w_ih_f, w_ih_b,
                                            b_ih_f, b_hh_f, b_ih_b, b_hh_b);
    k_lstm<<<128, 256, SMEM2>>>(w_hh_f, w_hh_b);
    k_emis<<<8192, 256>>>(lin_w, lin_b);
    k_crf<<<4, 1024>>>(y, st, en, tr);
    k_finsum<<<1, 32>>>((float*)d_out);
}

// round 17
// speedup vs baseline: 1.4287x; 1.0093x over previous
#include <cuda_runtime.h>
#include <cstdint>

#define Bq   128
#define Sq   512
#define Eq   256
#define HDq  256
#define Gq   1024
#define NTq  9

// ---- scratch (device globals; no allocation allowed) ----
__device__ float g_xg[2][Sq][Bq][Gq];        // [dir][s][b][p] permuted gates
__device__ float g_h[Bq][Sq][2*HDq];         // [b][s][dir*256+j]
__device__ float g_em[Bq][Sq][NTq];          // emissions
__device__ int   g_len[Bq];
__device__ unsigned g_cnt[2][8];             // per-(dir,batch-group) step counters
__device__ float g_llh[Bq];

typedef unsigned long long ull;

__device__ __forceinline__ ull pk2(float x, float y){
    ull r; asm("mov.b64 %0, {%1, %2};" : "=l"(r) : "f"(x), "f"(y)); return r;
}
__device__ __forceinline__ float2 up2(ull v){
    float2 r; asm("mov.b64 {%0, %1}, %2;" : "=f"(r.x), "=f"(r.y) : "l"(v)); return r;
}
__device__ __forceinline__ ull fma2(ull a, ull b, ull c){
    ull d; asm("fma.rn.f32x2 %0, %1, %2, %3;" : "=l"(d) : "l"(a), "l"(b), "l"(c)); return d;
}
__device__ __forceinline__ float tanhfast(float x){
    float y; asm("tanh.approx.f32 %0, %1;" : "=f"(y) : "f"(x)); return y;
}
__device__ __forceinline__ float sigf(float x){ return 0.5f*tanhfast(0.5f*x) + 0.5f; }

__device__ __forceinline__ uint32_t smem_u32(const void* p){
    uint32_t a;
    asm("{ .reg .u64 t; cvta.to.shared.u64 t, %1; cvt.u32.u64 %0, t; }"
        : "=r"(a) : "l"(p));
    return a;
}
__device__ __forceinline__ void cpasync16(uint32_t dst, const void* src){
    asm volatile("cp.async.ca.shared.global [%0], [%1], 16;" :: "r"(dst), "l"(src));
}
__device__ __forceinline__ void barh(int id){
    asm volatile("bar.sync %0, 128;" :: "r"(id) : "memory");
}

// ---------------------------------------------------------------------------
// prep: reset barrier counters, detect mask dtype, compute per-row lengths
// ---------------------------------------------------------------------------
__global__ void k_prep(const void* __restrict__ mask){
    const int b = threadIdx.x;
    if (b < 16) g_cnt[b >> 3][b & 7] = 0u;
    const unsigned char* m8 = (const unsigned char*)mask;
    const bool u8 = (m8[1] != 0);
    const int* m32 = (const int*)mask;
    int cnt = 0;
    for (int s = 0; s < Sq; s++)
        cnt += u8 ? (m8[b*Sq + s] != 0) : (m32[b*Sq + s] != 0);
    g_len[b] = cnt;
}

// no-op: put ncu's profiled slot (4th launch) on k_lstm
__global__ void k_nop(){}

// ---------------------------------------------------------------------------
// input projection: R6 config (best measured) — 8x8/thread, 2 CTAs/SM,
// float2 A-loads, f32x2 packed FMA
// permutation: p = j*4 + q  (q in {i,f,g,o}), r0 = q*256 + j
// ---------------------------------------------------------------------------
__global__ void __launch_bounds__(256,2) k_inproj(
    const int*   __restrict__ X,   const float* __restrict__ emb,
    const float* __restrict__ wf,  const float* __restrict__ wb,
    const float* __restrict__ bif, const float* __restrict__ bhf,
    const float* __restrict__ bib, const float* __restrict__ bhb)
{
    extern __shared__ float sm[];
    float* As = sm;                 // [128][68]
    float* Bs = sm + 128*68;        // [64][132] (transposed weights)
    const int s   = blockIdx.x;
    const int nt  = blockIdx.y;
    const int dir = nt >> 3;
    const float* __restrict__ w = dir ? wb : wf;
    const int t  = threadIdx.x;
    const int ty = t >> 4, tx = t & 15;

    const int ar = t >> 1, ah = t & 1;
    const int token = X[ar*Sq + s];
    const float4* asrc = reinterpret_cast<const float4*>(emb + (size_t)token*Eq);

    const int bn = t & 127, bhv = t >> 7;
    const int p_b  = ((nt & 7) * 128) + bn;
    const int r0_b = (p_b & 3)*HDq + (p_b >> 2);
    const float4* bsrc = reinterpret_cast<const float4*>(w + (size_t)r0_b*Eq);

    ull acc2[8][4];
    #pragma unroll
    for (int i = 0; i < 8; i++)
        #pragma unroll
        for (int j = 0; j < 4; j++) acc2[i][j] = 0ull;

    for (int kt = 0; kt < 4; kt++){
        {
            float4* adst = reinterpret_cast<float4*>(As + ar*68 + ah*32);
            const float4* a4 = asrc + kt*16 + ah*8;
            #pragma unroll
            for (int i = 0; i < 8; i++) adst[i] = a4[i];
        }
        {
            const float4* b4 = bsrc + kt*16 + bhv*8;
            #pragma unroll
            for (int i = 0; i < 8; i++){
                float4 v = b4[i];
                int k0 = bhv*32 + i*4;
                Bs[(k0+0)*132 + bn] = v.x;
                Bs[(k0+1)*132 + bn] = v.y;
                Bs[(k0+2)*132 + bn] = v.z;
                Bs[(k0+3)*132 + bn] = v.w;
            }
        }
        __syncthreads();
        #pragma unroll 2
        for (int k = 0; k < 64; k += 2){
            ulonglong2 b00 = *reinterpret_cast<ulonglong2*>(Bs + k*132 + tx*8);
            ulonglong2 b01 = *reinterpret_cast<ulonglong2*>(Bs + k*132 + tx*8 + 4);
            ulonglong2 b10 = *reinterpret_cast<ulonglong2*>(Bs + (k+1)*132 + tx*8);
            ulonglong2 b11 = *reinterpret_cast<ulonglong2*>(Bs + (k+1)*132 + tx*8 + 4);
            #pragma unroll
            for (int i = 0; i < 8; i++){
                float2 av = *reinterpret_cast<const float2*>(As + (ty*8+i)*68 + k);
                ull a0 = pk2(av.x, av.x);
                ull a1 = pk2(av.y, av.y);
                acc2[i][0] = fma2(a0, b00.x, acc2[i][0]);
                acc2[i][1] = fma2(a0, b00.y, acc2[i][1]);
                acc2[i][2] = fma2(a0, b01.x, acc2[i][2]);
                acc2[i][3] = fma2(a0, b01.y, acc2[i][3]);
                acc2[i][0] = fma2(a1, b10.x, acc2[i][0]);
                acc2[i][1] = fma2(a1, b10.y, acc2[i][1]);
                acc2[i][2] = fma2(a1, b11.x, acc2[i][2]);
                acc2[i][3] = fma2(a1, b11.y, acc2[i][3]);
            }
        }
        __syncthreads();
    }

    const float* bi  = dir ? bib : bif;
    const float* bh2 = dir ? bhb : bhf;
    const int pbase = (nt & 7)*128 + tx*8;
    float bias[8];
    #pragma unroll
    for (int j = 0; j < 8; j++){
        int p  = pbase + j;
        int r0 = (p & 3)*HDq + (p >> 2);
        bias[j] = bi[r0] + bh2[r0];
    }
    #pragma unroll
    for (int i = 0; i < 8; i++){
        int bidx = ty*8 + i;
        float* dst = &g_xg[dir][s][bidx][pbase];
        float2 v0 = up2(acc2[i][0]);
        float2 v1 = up2(acc2[i][1]);
        float2 v2 = up2(acc2[i][2]);
        float2 v3 = up2(acc2[i][3]);
        float4 o0 = make_float4(v0.x+bias[0], v0.y+bias[1], v1.x+bias[2], v1.y+bias[3]);
        float4 o1 = make_float4(v2.x+bias[4], v2.y+bias[5], v3.x+bias[6], v3.y+bias[7]);
        reinterpret_cast<float4*>(dst)[0] = o0;
        reinterpret_cast<float4*>(dst)[1] = o1;
    }
}

// ---------------------------------------------------------------------------
// BiLSTM recurrence, DIRECTION-INTERLEAVED:
// 128 CTAs = 8 batch-groups(16 rows) x 16 gate-slices(64 cols).
// Warps 0-3 = forward half, warps 4-7 = backward half (same bg, sl).
// Each SMSP hosts 1 fwd + 1 bwd warp: when one half blocks on its named
// barrier (poll/gather), the other half's warps keep the FMA pipe busy.
// Sync per (dir,bg): 16 slice-CTAs, release/acquire counter; R6-style
// chunked cp.async h gather overlapped with GEMM halves, per half.
// permutation: p = j*4 + q (q in {i,f,g,o}), source row r0 = q*256 + j
// ---------------------------------------------------------------------------
__global__ void __launch_bounds__(256,1) k_lstm(
    const float* __restrict__ whf, const float* __restrict__ whb)
{
    extern __shared__ float sm[];
    // Ws: [2][256][68] (64 cols used), Hs: [2][16][260]
    const int cta = blockIdx.x;
    const int bg  = cta >> 4;        // 0..7  (16 rows)
    const int sl  = cta & 15;        // 0..15 (64 gate cols)
    const int t   = threadIdx.x;
    const int dir = t >> 7;          // warps 0-3 fwd, 4-7 bwd
    const int ht  = t & 127;
    float* Ws = sm + dir*(256*68);
    float* Hs = sm + 2*256*68 + dir*(16*260);
    const float* __restrict__ w = dir ? whb : whf;
    unsigned* cntp = &g_cnt[dir][bg];
    const int bid = dir + 1;         // named barrier id (1 or 2)
    const uint32_t hs_u32 = smem_u32(Hs);

    // ---- load weight slice (64 permuted cols, full k), transposed ----
    {
        int c  = ht & 63;
        int kh = ht >> 6;            // 0..1
        int p  = sl*64 + c;
        int r0 = (p & 3)*HDq + (p >> 2);
        const float4* src = reinterpret_cast<const float4*>(w + (size_t)r0*HDq) + kh*32;
        #pragma unroll
        for (int i = 0; i < 32; i++){
            float4 v = src[i];
            int k0 = kh*128 + i*4;
            Ws[(k0+0)*68 + c] = v.x;
            Ws[(k0+1)*68 + c] = v.y;
            Ws[(k0+2)*68 + c] = v.z;
            Ws[(k0+3)*68 + c] = v.w;
        }
    }
    __syncthreads();   // one full-CTA sync; afterwards halves are independent

    // ---- thread tile (within half): 2 rows x 1 quad ----
    const int warp_h = ht >> 5, lane = ht & 31;
    const int rh = warp_h >> 1, cb = warp_h & 1;
    const int rp = lane >> 3, c4 = lane & 7;
    const int bcol = cb*32 + c4*4;      // quad cols (4 permuted gates)
    const int quad = cb*8 + c4;         // 0..15
    const int j    = sl*16 + quad;      // h element index
    const int r0   = rh*8 + rp*2;       // rows r0, r0+1
    const int bgl0 = bg*16 + r0;
    const int bgl1 = bgl0 + 1;
    const float* hrA = Hs + r0*260;
    const float* hrB = Hs + (r0+1)*260;

    float cA = 0.f, cB = 0.f;

    // prefetch x for step 0
    int tt0 = dir ? (Sq-1) : 0;
    float4 xA = *reinterpret_cast<const float4*>(&g_xg[dir][tt0][bgl0][sl*64 + bcol]);
    float4 xB = *reinterpret_cast<const float4*>(&g_xg[dir][tt0][bgl1][sl*64 + bcol]);

    for (int step = 0; step < Sq; step++){
        const int tt = dir ? (Sq-1-step) : step;

        ull aA0 = pk2(xA.x, xA.y), aA1 = pk2(xA.z, xA.w);
        ull aB0 = pk2(xB.x, xB.y), aB1 = pk2(xB.z, xB.w);

        if (step){
            // two GEMM halves, each gated on its cp.async chunk
            #pragma unroll
            for (int half = 0; half < 2; half++){
                if (half == 0){
                    asm volatile("cp.async.wait_group 1;" ::: "memory");
                } else {
                    asm volatile("cp.async.wait_group 0;" ::: "memory");
                }
                barh(bid);
                const int kbeg = half*128;
                #pragma unroll 2
                for (int k = kbeg; k < kbeg+128; k += 4){
                    float4 hA4 = *reinterpret_cast<const float4*>(hrA + k);
                    float4 hB4 = *reinterpret_cast<const float4*>(hrB + k);
                    ulonglong2 w0 = *reinterpret_cast<const ulonglong2*>(Ws + (k+0)*68 + bcol);
                    {   ull a = pk2(hA4.x, hA4.x), b = pk2(hB4.x, hB4.x);
                        aA0 = fma2(a, w0.x, aA0);  aA1 = fma2(a, w0.y, aA1);
                        aB0 = fma2(b, w0.x, aB0);  aB1 = fma2(b, w0.y, aB1); }
                    ulonglong2 w1 = *reinterpret_cast<const ulonglong2*>(Ws + (k+1)*68 + bcol);
                    {   ull a = pk2(hA4.y, hA4.y), b = pk2(hB4.y, hB4.y);
                        aA0 = fma2(a, w1.x, aA0);  aA1 = fma2(a, w1.y, aA1);
                        aB0 = fma2(b, w1.x, aB0);  aB1 = fma2(b, w1.y, aB1); }
                    ulonglong2 w2 = *reinterpret_cast<const ulonglong2*>(Ws + (k+2)*68 + bcol);
                    {   ull a = pk2(hA4.z, hA4.z), b = pk2(hB4.z, hB4.z);
                        aA0 = fma2(a, w2.x, aA0);  aA1 = fma2(a, w2.y, aA1);
                        aB0 = fma2(b, w2.x, aB0);  aB1 = fma2(b, w2.y, aB1); }
                    ulonglong2 w3 = *reinterpret_cast<const ulonglong2*>(Ws + (k+3)*68 + bcol);
                    {   ull a = pk2(hA4.w, hA4.w), b = pk2(hB4.w, hB4.w);
                        aA0 = fma2(a, w3.x, aA0);  aA1 = fma2(a, w3.y, aA1);
                        aB0 = fma2(b, w3.x, aB0);  aB1 = fma2(b, w3.y, aB1); }
                }
            }
        }
        // gates (i,f) in *0, (g,o) in *1; A = row0, B = row1
        float2 gA0 = up2(aA0), gA1 = up2(aA1);
        float2 gB0 = up2(aB0), gB1 = up2(aB1);
        cA = sigf(gA0.y)*cA + sigf(gA0.x)*tanhfast(gA1.x);
        float hA = sigf(gA1.y)*tanhfast(cA);
        cB = sigf(gB0.y)*cB + sigf(gB0.x)*tanhfast(gB1.x);
        float hB = sigf(gB1.y)*tanhfast(cB);

        g_h[bgl0][tt][dir*HDq + j] = hA;
        g_h[bgl1][tt][dir*HDq + j] = hB;

        if (step + 1 < Sq){
            const int tn = dir ? (Sq-2-step) : (step+1);
            // prefetch next step's x (hidden behind the poll)
            xA = *reinterpret_cast<const float4*>(&g_xg[dir][tn][bgl0][sl*64 + bcol]);
            xB = *reinterpret_cast<const float4*>(&g_xg[dir][tn][bgl1][sl*64 + bcol]);

            // half-local barrier: release-arrive, acquire-poll (16 CTAs)
            barh(bid);
            if (ht == 0){
                asm volatile("red.release.gpu.global.add.u32 [%0], %1;"
                             :: "l"(cntp), "r"(1u) : "memory");
                const unsigned target = 16u*(unsigned)(step+1);
                unsigned v;
                do {
                    asm volatile("ld.acquire.gpu.global.u32 %0, [%1];"
                                 : "=r"(v) : "l"(cntp) : "memory");
                } while (v < target);
            }
            barh(bid);

            // issue chunked h gather (2 groups of 128 k each); waited at next
            // step's GEMM halves. Per chunk: 512 float4 / 128 threads = 4 each.
            #pragma unroll
            for (int c = 0; c < 2; c++){
                #pragma unroll
                for (int i = 0; i < 4; i++){
                    int idx = ht + i*128;         // 0..511
                    int r   = idx >> 5;           // 0..15
                    int jjl = idx & 31;
                    int jj  = c*32 + jjl;         // float4 index: k = jj*4
                    cpasync16(hs_u32 + (uint32_t)((r*260 + jj*4)*4),
                              &g_h[bg*16 + r][tt][dir*HDq + jj*4]);
                }
                asm volatile("cp.async.commit_group;" ::: "memory");
            }
        }
    }
}

// ---------------------------------------------------------------------------
// emissions — float4 loads
// ---------------------------------------------------------------------------
__global__ void __launch_bounds__(256) k_emis(
    const float* __restrict__ lin_w, const float* __restrict__ lin_b)
{
    __shared__ float ws[NTq*512];
    const int t = threadIdx.x;
    for (int i = t; i < NTq*512; i += 256) ws[i] = lin_w[i];
    __syncthreads();
    const int warp = t >> 5, lane = t & 31;
    const int pos = blockIdx.x*8 + warp;
    const int b = pos >> 9, s = pos & 511;
    const float* orow = &g_h[b][s][0];
    float acc[NTq];
    #pragma unroll
    for (int k = 0; k < NTq; k++) acc[k] = 0.f;
    #pragma unroll
    for (int it = 0; it < 4; it++){
        float4 ov = *reinterpret_cast<const float4*>(orow + it*128 + lane*4);
        #pragma unroll
        for (int k = 0; k < NTq; k++){
            float4 wv = *reinterpret_cast<const float4*>(ws + k*512 + it*128 + lane*4);
            acc[k] += ov.x*wv.x + ov.y*wv.y + ov.z*wv.z + ov.w*wv.w;
        }
    }
    #pragma unroll
    for (int k = 0; k < NTq; k++){
        #pragma unroll
        for (int off = 16; off > 0; off >>= 1)
            acc[k] += __shfl_xor_sync(0xffffffffu, acc[k], off);
    }
    if (lane < NTq){
        float v = 0.f;
        #pragma unroll
        for (int k = 0; k < NTq; k++) if (lane == k) v = acc[k];
        g_em[b][s][lane] = v + lin_b[lane];
    }
}

// ---------------------------------------------------------------------------
// CRF log-likelihood: one warp per batch row
// ---------------------------------------------------------------------------
__global__ void __launch_bounds__(1024) k_crf(
    const int*   __restrict__ y,
    const float* __restrict__ st, const float* __restrict__ en,
    const float* __restrict__ tr)
{
    const int t = threadIdx.x;
    const int warp = t >> 5, lane = t & 31;
    const int b = blockIdx.x*32 + warp;
    const int L = g_len[b];
    const int* yr = y + b*Sq;
    const float* emr = &g_em[b][0][0];
    const int lc = (lane < NTq) ? lane : (NTq-1);

    float num = 0.f;
    for (int tt = lane; tt < L; tt += 32){
        int yt = yr[tt];
        num += emr[tt*NTq + yt];
        if (tt > 0) num += tr[yr[tt-1]*NTq + yt];
    }
    #pragma unroll
    for (int off = 16; off > 0; off >>= 1)
        num += __shfl_xor_sync(0xffffffffu, num, off);

    float trv[NTq];
    #pragma unroll
    for (int i = 0; i < NTq; i++) trv[i] = tr[i*NTq + lc];
    float alpha = st[lc] + emr[lc];
    for (int tt = 1; tt < L; tt++){
        float vals[NTq]; float m = -3.0e38f;
        #pragma unroll
        for (int i = 0; i < NTq; i++){
            float ai = __shfl_sync(0xffffffffu, alpha, i);
            vals[i] = ai + trv[i];
            m = fmaxf(m, vals[i]);
        }
        float ssum = 0.f;
        #pragma unroll
        for (int i = 0; i < NTq; i++) ssum += __expf(vals[i]-m);
        alpha = m + __logf(ssum) + emr[tt*NTq + lc];
    }
    float v = (lane < NTq) ? (alpha + en[lane]) : -3.0e38f;
    float m = v;
    #pragma unroll
    for (int off = 16; off > 0; off >>= 1)
        m = fmaxf(m, __shfl_xor_sync(0xffffffffu, m, off));
    float e = __expf(v - m);
    #pragma unroll
    for (int off = 16; off > 0; off >>= 1)
        e += __shfl_xor_sync(0xffffffffu, e, off);
    float den = m + __logf(e);
    if (lane == 0)
        g_llh[b] = num + st[yr[0]] + en[yr[L-1]] - den;
}

__global__ void k_finsum(float* __restrict__ out){
    const int lane = threadIdx.x;
    float s1 = g_llh[lane] + g_llh[lane+32] + g_llh[lane+64] + g_llh[lane+96];
    #pragma unroll
    for (int off = 16; off > 0; off >>= 1)
        s1 += __shfl_xor_sync(0xffffffffu, s1, off);
    if (lane == 0) out[0] = s1;
}

// ---------------------------------------------------------------------------
extern "C" void kernel_launch(void* const* d_in, const int* in_sizes, int n_in,
                              void* d_out, int out_size)
{
    const int*   X      = (const int*)  d_in[0];
    const int*   y      = (const int*)  d_in[1];
    const void*  mask   =               d_in[2];
    const float* emb    = (const float*)d_in[3];
    const float* w_ih_f = (const float*)d_in[4];
    const float* w_hh_f = (const float*)d_in[5];
    const float* b_ih_f = (const float*)d_in[6];
    const float* b_hh_f = (const float*)d_in[7];
    const float* w_ih_b = (const float*)d_in[8];
    const float* w_hh_b = (const float*)d_in[9];
    const float* b_ih_b = (const float*)d_in[10];
    const float* b_hh_b = (const float*)d_in[11];
    const float* lin_w  = (const float*)d_in[12];
    const float* lin_b  = (const float*)d_in[13];
    const float* st     = (const float*)d_in[14];
    const float* en     = (const float*)d_in[15];
    const float* tr     = (const float*)d_in[16];

    const int SMEM1 = (128*68 + 64*132) * 4;        // 68,608 B
    const int SMEM2 = (2*256*68 + 2*16*260) * 4;    // 172,544 B
    cudaFuncSetAttribute(k_inproj, cudaFuncAttributeMaxDynamicSharedMemorySize, SMEM1);
    cudaFuncSetAttribute(k_lstm,   cudaFuncAttributeMaxDynamicSharedMemorySize, SMEM2);

    k_prep<<<1, 128>>>(mask);
    k_nop<<<1, 32>>>();   // ncu profiles the 4th launch -> k_lstm
    k_inproj<<<dim3(512, 16), 256, SMEM1>>>(X, emb, w_ih_f, w_ih_b,
                                            b_ih_f, b_hh_f, b_ih_b, b_hh_b);
    k_lstm<<<128, 256, SMEM2>>>(w_hh_f, w_hh_b);
    k_emis<<<8192, 256>>>(lin_w, lin_b);
    k_crf<<<4, 1024>>>(y, st, en, tr);
    k_finsum<<<1, 32>>>((float*)d_out);
}